// round 9
// baseline (speedup 1.0000x reference)
#include <cuda_runtime.h>
#include <cuda_bf16.h>
#include <cstdint>

#define NUM_ENT 40000
#define ED      256
#define FD      768
#define BATCH   32
#define NE_OUT  (NUM_ENT + 1)

typedef unsigned long long u64;

__device__ __nv_bfloat16  g_Bb[FD * ED];       // proj_W bf16 [n][k]
__device__ float          g_qn[64 * ED];       // normalized query rows (64 slots)
__device__ u64            g_qsum2[ED * 16];    // qsum packed [d][bp] = {b=2bp, 2bp+1}

// ---------------- helpers ----------------
__device__ __forceinline__ u64 addf32x2(u64 a, u64 b) {
    u64 r;
    asm("add.rn.f32x2 %0, %1, %2;" : "=l"(r) : "l"(a), "l"(b));
    return r;
}
__device__ __forceinline__ u64 pack2(float x) {
    u64 r;
    asm("mov.b64 %0, {%1,%1};" : "=l"(r) : "f"(x));
    return r;
}
__device__ __forceinline__ void ldsm4(uint32_t r[4], uint32_t addr) {
    asm volatile("ldmatrix.sync.aligned.m8n8.x4.shared.b16 {%0,%1,%2,%3}, [%4];"
                 : "=r"(r[0]), "=r"(r[1]), "=r"(r[2]), "=r"(r[3])
                 : "r"(addr));
}
__device__ __forceinline__ void mma16816(float c[4], const uint32_t a[4],
                                         uint32_t b0, uint32_t b1) {
    asm volatile(
        "mma.sync.aligned.m16n8k16.row.col.f32.bf16.bf16.f32 "
        "{%0,%1,%2,%3}, {%4,%5,%6,%7}, {%8,%9}, {%0,%1,%2,%3};"
        : "+f"(c[0]), "+f"(c[1]), "+f"(c[2]), "+f"(c[3])
        : "r"(a[0]), "r"(a[1]), "r"(a[2]), "r"(a[3]), "r"(b0), "r"(b1));
}
__device__ __forceinline__ uint32_t smaddr(const void* p) {
    return (uint32_t)__cvta_generic_to_shared(p);
}

__device__ __forceinline__ int decode_one(const void* ids_raw, const int* mp_ptr,
                                          int b, int j) {
    const int* p = (const int*)ids_raw;
    bool is64 = true;
    for (int i = 1; i < BATCH * 3 * 2; i += 2)
        if (i < BATCH * 3 * 2 && (i >> 1) < BATCH * 3) {
            if (p[i] != 0) { is64 = false; break; }
        }
    int mp = 2;
    if (mp_ptr) {
        int im = *mp_ptr;
        if (im >= 0 && im < 3) mp = im;
        else {
            float f = __int_as_float(im);
            if (f >= 0.f && f < 3.f) mp = (int)f;
        }
    }
    int col3 = (j < mp) ? j : j + 1;
    int idx  = b * 3 + col3;
    return is64 ? (int)((const long long*)ids_raw)[idx] : p[idx];
}

// ---------------- prep kernels ----------------
__global__ void convB_kernel(const float* __restrict__ W) {
    int i = blockIdx.x * 256 + threadIdx.x;
    if (i < FD * ED) g_Bb[i] = __float2bfloat16(W[i]);
}

// one block per query slot s (= b*2 + j): project/gather unity row, normalize
__global__ void __launch_bounds__(256) proj_gather_kernel(
        const float* __restrict__ ent, const float* __restrict__ other,
        const float* __restrict__ W,
        const void* __restrict__ ids_raw, const int* __restrict__ mp_ptr) {
    __shared__ float a_sm[FD];
    __shared__ float v_sm[ED];
    __shared__ float red[8];
    __shared__ int   s_id;
    const int s = blockIdx.x, tid = threadIdx.x;
    const int warp = tid >> 5, lane = tid & 31;

    if (tid == 0) s_id = decode_one(ids_raw, mp_ptr, s >> 1, s & 1);
    __syncthreads();
    const int id = s_id;

    if (id >= 1 && id <= NUM_ENT) {
        const float* arow = ent + (size_t)(id - 1) * FD;
        for (int i = tid; i < FD; i += 256) a_sm[i] = arow[i];
        __syncthreads();
#pragma unroll 1
        for (int nn = 0; nn < 32; nn++) {
            int n = warp * 32 + nn;
            const float* wr = W + (size_t)n * FD;
            float p = 0.f;
#pragma unroll
            for (int t = 0; t < FD / 32; t++)
                p += wr[lane + t * 32] * a_sm[lane + t * 32];
#pragma unroll
            for (int o = 16; o > 0; o >>= 1)
                p += __shfl_xor_sync(0xffffffffu, p, o);
            if (lane == 0) v_sm[n] = p;
        }
    } else {
        int r = (id == 0) ? 0 : (id - NUM_ENT);
        if (tid < ED) v_sm[tid] = other[r * ED + tid];
        __syncthreads();   // match barrier count not needed (divergent block-level ok: all threads take same branch)
    }
    __syncthreads();

    float v = v_sm[tid];
    float ss = v * v;
#pragma unroll
    for (int o = 16; o > 0; o >>= 1) ss += __shfl_xor_sync(0xffffffffu, ss, o);
    if (lane == 0) red[warp] = ss;
    __syncthreads();
    float tot = 0.f;
#pragma unroll
    for (int w = 0; w < 8; w++) tot += red[w];
    float rn = 1.0f / fmaxf(sqrtf(tot), 1e-12f);
    g_qn[s * ED + tid] = v * rn;
}

// one block: build qsum packed layout + out column 0 (unity row 0 = other[0])
__global__ void __launch_bounds__(256) combine_kernel(
        const float* __restrict__ other, float* __restrict__ out) {
    __shared__ float part[8][32];
    const int d = threadIdx.x, warp = d >> 5;

    float q[BATCH];
#pragma unroll
    for (int b = 0; b < BATCH; b++)
        q[b] = g_qn[(2 * b) * ED + d] + g_qn[(2 * b + 1) * ED + d];
#pragma unroll
    for (int bp = 0; bp < 16; bp++) {
        u64 r;
        asm("mov.b64 %0, {%1,%2};" : "=l"(r) : "f"(q[2 * bp]), "f"(q[2 * bp + 1]));
        g_qsum2[d * 16 + bp] = r;
    }
    float o0 = other[d];
    float ab[BATCH];
#pragma unroll
    for (int b = 0; b < BATCH; b++) ab[b] = fabsf(q[b] - o0);
#pragma unroll
    for (int b = 0; b < BATCH; b++) {
        float t = ab[b];
#pragma unroll
        for (int o = 16; o > 0; o >>= 1) t += __shfl_xor_sync(0xffffffffu, t, o);
        if ((d & 31) == 0) part[warp][b] = t;
    }
    __syncthreads();
    if (d < BATCH) {
        float s = 0.f;
#pragma unroll
        for (int w = 0; w < 8; w++) s += part[w][d];
        out[(size_t)d * NE_OUT] = -s;
    }
}

// ---------------- fused GEMM + score ----------------
// R3 GEMM (BM=128, BN=256, BK=32, 512 thr, 16 warps 4m x 4n, warp tile 32x64).
// Epilogue: per d-chunk of 64, stage -acc to s_out[64][132], then all warps
// compute score partials vs qsum (warp = 32 entities x 4 batch-pairs).
#define BM       128
#define BK       32
#define ASTRIDE  40
#define A_ST     (BM * ASTRIDE)
#define B_ST     (ED * ASTRIDE)
#define GEMM_BF  (2 * A_ST + 2 * B_ST)         // bf16 elems = 30720
#define QSM_OFF  (GEMM_BF * 2)                 // byte offset 61440
#define GEMM_SMEM (QSM_OFF + ED * 16 * 8)      // + 32768 = 94208

__global__ void __launch_bounds__(512, 1) gemm_score_kernel(
        const float* __restrict__ A, float* __restrict__ out) {
    extern __shared__ __nv_bfloat16 sm[];
    __nv_bfloat16* sA = sm;
    __nv_bfloat16* sB = sm + 2 * A_ST;
    u64* qsm = (u64*)((char*)sm + QSM_OFF);

    const int tid  = threadIdx.x;
    const int lane = tid & 31;
    const int warp = tid >> 5;
    const int wm   = warp >> 2;
    const int wn   = warp & 3;
    const int bm0  = blockIdx.x * BM;

    // stage qsum into smem (visible after first __syncthreads)
#pragma unroll
    for (int i = 0; i < 8; i++) qsm[tid + i * 512] = g_qsum2[tid + i * 512];

    float acc[2][8][4];
#pragma unroll
    for (int i = 0; i < 2; i++)
#pragma unroll
        for (int j = 0; j < 8; j++)
#pragma unroll
            for (int k = 0; k < 4; k++) acc[i][j][k] = 0.f;

    const int arow = tid >> 2, af4 = (tid & 3) * 2;
    const bool aok = (bm0 + arow) < NUM_ENT;
    const float* arow_p = A + (size_t)(aok ? bm0 + arow : 0) * FD;
    const int brow = tid >> 1, bq4 = (tid & 1) * 2;

    float4 va[2];
    uint4  vb[2];
    auto loadG = [&](int kc) {
#pragma unroll
        for (int i = 0; i < 2; i++) {
            if (aok) va[i] = *(const float4*)(arow_p + kc + (af4 + i) * 4);
            else     va[i] = make_float4(0.f, 0.f, 0.f, 0.f);
        }
#pragma unroll
        for (int i = 0; i < 2; i++)
            vb[i] = *(const uint4*)((const __nv_bfloat16*)g_Bb +
                                    (size_t)brow * FD + kc + (bq4 + i) * 8);
    };
    auto stsStage = [&](int st) {
#pragma unroll
        for (int i = 0; i < 2; i++) {
            __nv_bfloat162 p0 = __floats2bfloat162_rn(va[i].x, va[i].y);
            __nv_bfloat162 p1 = __floats2bfloat162_rn(va[i].z, va[i].w);
            uint2 u;
            u.x = *(uint32_t*)&p0;
            u.y = *(uint32_t*)&p1;
            *(uint2*)&sA[st * A_ST + arow * ASTRIDE + (af4 + i) * 4] = u;
        }
#pragma unroll
        for (int i = 0; i < 2; i++)
            *(uint4*)&sB[st * B_ST + brow * ASTRIDE + (bq4 + i) * 8] = vb[i];
    };

    const int quad = lane >> 3, l8 = lane & 7;
    const int arow_l = (quad & 1) * 8 + l8;
    const int acol_q = (quad >> 1) * 8;
    const int brow_l = (quad >> 1) * 8 + l8;
    const int bcol_q = (quad & 1) * 8;

    auto mmaStage = [&](int st) {
#pragma unroll
        for (int ks = 0; ks < 2; ks++) {
            const int k0 = ks * 16;
            uint32_t a[2][4], b[4][4];
#pragma unroll
            for (int mf = 0; mf < 2; mf++) {
                uint32_t ad = smaddr(&sA[st * A_ST +
                                         (wm * 32 + mf * 16 + arow_l) * ASTRIDE +
                                         k0 + acol_q]);
                ldsm4(a[mf], ad);
            }
#pragma unroll
            for (int nf2 = 0; nf2 < 4; nf2++) {
                uint32_t ad = smaddr(&sB[st * B_ST +
                                         (wn * 64 + nf2 * 16 + brow_l) * ASTRIDE +
                                         k0 + bcol_q]);
                ldsm4(b[nf2], ad);
            }
#pragma unroll
            for (int mf = 0; mf < 2; mf++)
#pragma unroll
                for (int nt = 0; nt < 8; nt++)
                    mma16816(acc[mf][nt], a[mf],
                             b[nt >> 1][(nt & 1) * 2],
                             b[nt >> 1][(nt & 1) * 2 + 1]);
        }
    };

    const int NC = FD / BK;
    loadG(0);
    stsStage(0);
#pragma unroll 1
    for (int c = 0; c < NC; c++) {
        __syncthreads();
        const int cst = c & 1, nst = (c + 1) & 1;
        if (c + 1 < NC) loadG((c + 1) * BK);
        mmaStage(cst);
        if (c + 1 < NC) stsStage(nst);
    }
    __syncthreads();

    // fused epilogue: stage 64 d-rows (negated), then score partials
    float* s_out = (float*)sm;                 // 64*132*4 = 33792 B (< QSM_OFF)
    const int g = lane >> 2, tg = lane & 3;
    const int eblk = warp >> 2, bpq = warp & 3;
    u64 acc_sc[4] = {0ULL, 0ULL, 0ULL, 0ULL};
    const u64 MSK = 0x7FFFFFFF7FFFFFFFULL;

#pragma unroll 1
    for (int chunk = 0; chunk < 4; chunk++) {
        if (wn == chunk) {
#pragma unroll
            for (int mf = 0; mf < 2; mf++)
#pragma unroll
                for (int nt = 0; nt < 8; nt++) {
                    int srow = nt * 8 + tg * 2;
                    int scol = wm * 32 + mf * 16 + g;
                    s_out[srow * 132 + scol]           = -acc[mf][nt][0];
                    s_out[(srow + 1) * 132 + scol]     = -acc[mf][nt][1];
                    s_out[srow * 132 + scol + 8]       = -acc[mf][nt][2];
                    s_out[(srow + 1) * 132 + scol + 8] = -acc[mf][nt][3];
                }
        }
        __syncthreads();
        const u64* qbase = qsm + (size_t)chunk * 64 * 16 + bpq * 4;
        const float* sp = s_out + eblk * 32 + lane;
#pragma unroll 4
        for (int i = 0; i < 64; i++) {
            float ev = sp[i * 132];            // negated E value
            u64 e2 = pack2(ev);
            const u64* qr = qbase + (size_t)i * 16;
            ulonglong2 qa = *(const ulonglong2*)qr;
            ulonglong2 qb = *(const ulonglong2*)(qr + 2);
            acc_sc[0] = addf32x2(acc_sc[0], addf32x2(qa.x, e2) & MSK);
            acc_sc[1] = addf32x2(acc_sc[1], addf32x2(qa.y, e2) & MSK);
            acc_sc[2] = addf32x2(acc_sc[2], addf32x2(qb.x, e2) & MSK);
            acc_sc[3] = addf32x2(acc_sc[3], addf32x2(qb.y, e2) & MSK);
        }
        __syncthreads();
    }

    // write scores: entity m = bm0 + e  ->  out column m+1
    const int e = eblk * 32 + lane;
    if (bm0 + e < NUM_ENT) {
        float* dst = out + bm0 + 1 + e;
#pragma unroll
        for (int j = 0; j < 4; j++) {
            int bp = bpq * 4 + j;
            float lo = __int_as_float((int)(acc_sc[j] & 0xffffffffULL));
            float hi = __int_as_float((int)(acc_sc[j] >> 32));
            dst[(size_t)(2 * bp) * NE_OUT]     = -lo;
            dst[(size_t)(2 * bp + 1) * NE_OUT] = -hi;
        }
    }
}

// ---------------- launcher ----------------
extern "C" void kernel_launch(void* const* d_in, const int* in_sizes, int n_in,
                              void* d_out, int out_size) {
    const float* ent   = (const float*)d_in[0];
    const float* other = (const float*)d_in[1];
    const float* W     = (const float*)d_in[2];
    const void*  ids   = d_in[3];
    const int*   mp    = (n_in > 4) ? (const int*)d_in[4] : nullptr;

    cudaFuncSetAttribute(gemm_score_kernel,
                         cudaFuncAttributeMaxDynamicSharedMemorySize, GEMM_SMEM);

    convB_kernel<<<(FD * ED + 255) / 256, 256>>>(W);
    proj_gather_kernel<<<64, 256>>>(ent, other, W, ids, mp);
    combine_kernel<<<1, 256>>>(other, (float*)d_out);
    gemm_score_kernel<<<(NUM_ENT + BM - 1) / BM, 512, GEMM_SMEM>>>(
        ent, (float*)d_out);
}

// round 10
// speedup vs baseline: 1.4927x; 1.4927x over previous
#include <cuda_runtime.h>
#include <cuda_bf16.h>
#include <cstdint>

#define NUM_ENT 40000
#define ED      256
#define FD      768
#define BATCH   32
#define NE_OUT  (NUM_ENT + 1)
#define ET_LD   40128

typedef unsigned long long u64;

// g_Et stores NEGATED values. Column map:
//   col c in [0,40000) : -ent_proj[c] (unity row c+1)
//   col 40000+r        : -other_emb[r] (unity rows 0, 40001..40102)
__device__ float          g_Et[ED * ET_LD];
__device__ __nv_bfloat16  g_Bb[FD * ED];
__device__ float          g_qsum[ED * BATCH];
__device__ int            g_qcol[BATCH * 2];

// ---------------- helpers ----------------
__device__ __forceinline__ u64 addf32x2(u64 a, u64 b) {
    u64 r;
    asm("add.rn.f32x2 %0, %1, %2;" : "=l"(r) : "l"(a), "l"(b));
    return r;
}
__device__ __forceinline__ u64 pack2(float x) {
    u64 r;
    asm("mov.b64 %0, {%1,%1};" : "=l"(r) : "f"(x));
    return r;
}
__device__ __forceinline__ void ldsm4(uint32_t r[4], uint32_t addr) {
    asm volatile("ldmatrix.sync.aligned.m8n8.x4.shared.b16 {%0,%1,%2,%3}, [%4];"
                 : "=r"(r[0]), "=r"(r[1]), "=r"(r[2]), "=r"(r[3])
                 : "r"(addr));
}
__device__ __forceinline__ void mma16816(float c[4], const uint32_t a[4],
                                         uint32_t b0, uint32_t b1) {
    asm volatile(
        "mma.sync.aligned.m16n8k16.row.col.f32.bf16.bf16.f32 "
        "{%0,%1,%2,%3}, {%4,%5,%6,%7}, {%8,%9}, {%0,%1,%2,%3};"
        : "+f"(c[0]), "+f"(c[1]), "+f"(c[2]), "+f"(c[3])
        : "r"(a[0]), "r"(a[1]), "r"(a[2]), "r"(a[3]), "r"(b0), "r"(b1));
}
__device__ __forceinline__ uint32_t smaddr(const void* p) {
    return (uint32_t)__cvta_generic_to_shared(p);
}

// ---------------- prep kernels ----------------
__global__ void convB_kernel(const float* __restrict__ W) {
    int i = blockIdx.x * 256 + threadIdx.x;
    if (i < FD * ED) g_Bb[i] = __float2bfloat16(W[i]);
}
__global__ void fill_kernel(const float* __restrict__ other) {
    int i = blockIdx.x * 256 + threadIdx.x;
    if (i < 103 * ED) {
        int r = i / ED, d = i % ED;
        g_Et[d * ET_LD + NUM_ENT + r] = -other[i];
    }
}
__global__ void decode_ids_kernel(const void* __restrict__ ids_raw,
                                  const int* __restrict__ mp_ptr) {
    if (threadIdx.x != 0) return;
    const int* p = (const int*)ids_raw;
    bool is64 = true;
    for (int i = 1; i < BATCH * 3; i += 2)
        if (p[i] != 0) { is64 = false; break; }
    int mp = 2;
    if (mp_ptr) {
        int im = *mp_ptr;
        if (im >= 0 && im < 3) mp = im;
        else {
            float f = __int_as_float(im);
            if (f >= 0.f && f < 3.f) mp = (int)f;
        }
    }
    for (int b = 0; b < BATCH; b++)
        for (int j = 0; j < 2; j++) {
            int col3 = (j < mp) ? j : j + 1;
            int idx  = b * 3 + col3;
            int id   = is64 ? (int)((const long long*)ids_raw)[idx] : p[idx];
            int col  = (id == 0) ? NUM_ENT : (id <= NUM_ENT ? id - 1 : id);
            g_qcol[b * 2 + j] = col;
        }
}

// ---------------- GEMM: Et[n][bm0+m] = -sum_k A[m,k]*W[n,k] ----------------
// R3 skeleton, BK=64 (12 barriers). BM=128, BN=256, 512 threads (4m x 4n),
// warp tile 32x64. ASTRIDE=72 (64+8 pad). Half-split loads keep regs ~128.
#define BM       128
#define BK       64
#define ASTRIDE  72
#define A_ST     (BM * ASTRIDE)          // 9216 bf16
#define B_ST     (ED * ASTRIDE)          // 18432 bf16
#define GEMM_SMEM ((2 * A_ST + 2 * B_ST) * 2)   // 110592 B

__global__ void __launch_bounds__(512, 1) gemm_bf16_kernel(const float* __restrict__ A) {
    extern __shared__ __nv_bfloat16 sm[];
    __nv_bfloat16* sA = sm;
    __nv_bfloat16* sB = sm + 2 * A_ST;

    const int tid  = threadIdx.x;
    const int lane = tid & 31;
    const int warp = tid >> 5;
    const int wm   = warp >> 2;
    const int wn   = warp & 3;
    const int bm0  = blockIdx.x * BM;

    float acc[2][8][4];
#pragma unroll
    for (int i = 0; i < 2; i++)
#pragma unroll
        for (int j = 0; j < 8; j++)
#pragma unroll
            for (int k = 0; k < 4; k++) acc[i][j][k] = 0.f;

    float4 va[2];
    uint4  vb[2];

    // A: 128 rows x 16 f4-slots; s = tid + 512*(2h+i): row=s>>4, slot=s&15
    auto loadHalfA = [&](int kc, int h) {
#pragma unroll
        for (int i = 0; i < 2; i++) {
            int s = tid + 512 * (2 * h + i);
            int r = s >> 4, sl = s & 15;
            if (bm0 + r < NUM_ENT)
                va[i] = *(const float4*)(A + (size_t)(bm0 + r) * FD + kc + sl * 4);
            else
                va[i] = make_float4(0.f, 0.f, 0.f, 0.f);
        }
    };
    auto stsHalfA = [&](int st, int h) {
#pragma unroll
        for (int i = 0; i < 2; i++) {
            int s = tid + 512 * (2 * h + i);
            int r = s >> 4, sl = s & 15;
            __nv_bfloat162 p0 = __floats2bfloat162_rn(va[i].x, va[i].y);
            __nv_bfloat162 p1 = __floats2bfloat162_rn(va[i].z, va[i].w);
            uint32_t u0 = *(uint32_t*)&p0, u1 = *(uint32_t*)&p1;
            uint32_t ad = smaddr(&sA[st * A_ST + r * ASTRIDE + sl * 4]);
            asm volatile("st.shared.v2.b32 [%0], {%1,%2};"
                         :: "r"(ad), "r"(u0), "r"(u1) : "memory");
        }
    };
    // B: 256 rows x 8 u4-slots; s = tid + 512*(2h+i): row=s>>3, slot=s&7
    auto loadHalfB = [&](int kc, int h) {
#pragma unroll
        for (int i = 0; i < 2; i++) {
            int s = tid + 512 * (2 * h + i);
            int r = s >> 3, q = s & 7;
            vb[i] = *(const uint4*)((const __nv_bfloat16*)g_Bb +
                                    (size_t)r * FD + kc + q * 8);
        }
    };
    auto stsHalfB = [&](int st, int h) {
#pragma unroll
        for (int i = 0; i < 2; i++) {
            int s = tid + 512 * (2 * h + i);
            int r = s >> 3, q = s & 7;
            *(uint4*)&sB[st * B_ST + r * ASTRIDE + q * 8] = vb[i];
        }
    };

    const int quad = lane >> 3, l8 = lane & 7;
    const int arow_l = (quad & 1) * 8 + l8;
    const int acol_q = (quad >> 1) * 8;
    const int brow_l = (quad >> 1) * 8 + l8;
    const int bcol_q = (quad & 1) * 8;

    auto mmaSub = [&](int st, int ks) {
        const int k0 = ks * 16;
        uint32_t a[2][4], b[4][4];
#pragma unroll
        for (int mf = 0; mf < 2; mf++) {
            uint32_t ad = smaddr(&sA[st * A_ST +
                                     (wm * 32 + mf * 16 + arow_l) * ASTRIDE +
                                     k0 + acol_q]);
            ldsm4(a[mf], ad);
        }
#pragma unroll
        for (int nf2 = 0; nf2 < 4; nf2++) {
            uint32_t ad = smaddr(&sB[st * B_ST +
                                     (wn * 64 + nf2 * 16 + brow_l) * ASTRIDE +
                                     k0 + bcol_q]);
            ldsm4(b[nf2], ad);
        }
#pragma unroll
        for (int mf = 0; mf < 2; mf++)
#pragma unroll
            for (int nt = 0; nt < 8; nt++)
                mma16816(acc[mf][nt], a[mf],
                         b[nt >> 1][(nt & 1) * 2],
                         b[nt >> 1][(nt & 1) * 2 + 1]);
    };

    const int NC = FD / BK;    // 12
    // prologue: chunk 0 -> stage 0 (halves sequentially; regs reused)
    loadHalfA(0, 0); loadHalfB(0, 0); stsHalfA(0, 0); stsHalfB(0, 0);
    loadHalfA(0, 1); loadHalfB(0, 1); stsHalfA(0, 1); stsHalfB(0, 1);

#pragma unroll 1
    for (int c = 0; c < NC; c++) {
        __syncthreads();
        const int cst = c & 1, nst = cst ^ 1;
        const int kc1 = (c + 1) * BK;
        if (c + 1 < NC) { loadHalfA(kc1, 0); loadHalfB(kc1, 0); }
        mmaSub(cst, 0);
        mmaSub(cst, 1);
        if (c + 1 < NC) {
            stsHalfA(nst, 0); stsHalfB(nst, 0);
            loadHalfA(kc1, 1); loadHalfB(kc1, 1);
        }
        mmaSub(cst, 2);
        mmaSub(cst, 3);
        if (c + 1 < NC) { stsHalfA(nst, 1); stsHalfB(nst, 1); }
    }
    __syncthreads();

    // staged, coalesced epilogue: 4 chunks of 64 n-rows (chunk = wn), NEGATED
    float* s_out = (float*)sm;                 // [64][132] = 33.8 KB
    const int g = lane >> 2, tg = lane & 3;
#pragma unroll
    for (int chunk = 0; chunk < 4; chunk++) {
        if (wn == chunk) {
#pragma unroll
            for (int mf = 0; mf < 2; mf++)
#pragma unroll
                for (int nt = 0; nt < 8; nt++) {
                    int srow = nt * 8 + tg * 2;
                    int scol = wm * 32 + mf * 16 + g;
                    s_out[srow * 132 + scol]           = -acc[mf][nt][0];
                    s_out[(srow + 1) * 132 + scol]     = -acc[mf][nt][1];
                    s_out[srow * 132 + scol + 8]       = -acc[mf][nt][2];
                    s_out[(srow + 1) * 132 + scol + 8] = -acc[mf][nt][3];
                }
        }
        __syncthreads();
#pragma unroll
        for (int i = 0; i < 4; i++) {
            int idx = tid + i * 512;
            int n = idx >> 5, m4 = idx & 31;
            if (bm0 + m4 * 4 + 4 <= NUM_ENT) {
                float4 v = *(float4*)&s_out[n * 132 + m4 * 4];
                *(float4*)&g_Et[(size_t)(chunk * 64 + n) * ET_LD + bm0 + m4 * 4] = v;
            }
        }
        __syncthreads();
    }
}

// ---------------- query_sum ----------------
__global__ void __launch_bounds__(256) qsum_kernel() {
    __shared__ float s_red[2][8];
    const int b = blockIdx.x, tid = threadIdx.x;
    const int c0 = g_qcol[b * 2], c1 = g_qcol[b * 2 + 1];

    const int d = tid;
    float v0 = g_Et[d * ET_LD + c0];
    float v1 = g_Et[d * ET_LD + c1];
    float ss0 = v0 * v0, ss1 = v1 * v1;
#pragma unroll
    for (int o = 16; o > 0; o >>= 1) {
        ss0 += __shfl_xor_sync(0xffffffffu, ss0, o);
        ss1 += __shfl_xor_sync(0xffffffffu, ss1, o);
    }
    if ((tid & 31) == 0) { s_red[0][tid >> 5] = ss0; s_red[1][tid >> 5] = ss1; }
    __syncthreads();
    ss0 = 0.f; ss1 = 0.f;
#pragma unroll
    for (int w = 0; w < 8; w++) { ss0 += s_red[0][w]; ss1 += s_red[1][w]; }
    float r0 = -1.0f / fmaxf(sqrtf(ss0), 1e-12f);
    float r1 = -1.0f / fmaxf(sqrtf(ss1), 1e-12f);
    g_qsum[d * BATCH + b] = v0 * r0 + v1 * r1;
}

// ---------------- score: 1 col/thread, batched q-LDS ----------------
__global__ void __launch_bounds__(256) score_kernel(float* __restrict__ out) {
    __shared__ u64 sq[ED][4];
    const int tid = threadIdx.x;
    const int by  = blockIdx.y;

    {
        float4* dst = (float4*)&sq[0][0];
#pragma unroll
        for (int i = 0; i < 2; i++) {
            int idx = tid + i * 256;
            int d = idx >> 1, h = idx & 1;
            dst[d * 2 + h] = *(const float4*)(g_qsum + d * BATCH + by * 8 + h * 4);
        }
    }
    __syncthreads();

    const int c = blockIdx.x * 256 + tid;
    const bool active = (c <= NUM_ENT);
    const float* ecol = g_Et + (active ? c : 0);

    u64 acc[4];
#pragma unroll
    for (int i = 0; i < 4; i++) acc[i] = 0ULL;

    float cur[4], nxt[4];
#pragma unroll
    for (int j = 0; j < 4; j++) cur[j] = ecol[j * ET_LD];

    const u64 MSK = 0x7FFFFFFF7FFFFFFFULL;
    auto body = [&](int d0, const float cv[4]) {
        // batch q loads for the whole group first (8 x LDS.128)
        u64 q[4][4];
#pragma unroll
        for (int j = 0; j < 4; j++) {
            ulonglong2 t0 = *(const ulonglong2*)&sq[d0 + j][0];
            ulonglong2 t1 = *(const ulonglong2*)&sq[d0 + j][2];
            q[j][0] = t0.x; q[j][1] = t0.y; q[j][2] = t1.x; q[j][3] = t1.y;
        }
#pragma unroll
        for (int j = 0; j < 4; j++) {
            u64 e = pack2(cv[j]);
#pragma unroll
            for (int bp = 0; bp < 4; bp++)
                acc[bp] = addf32x2(acc[bp], addf32x2(q[j][bp], e) & MSK);
        }
    };

    for (int d0 = 0; d0 < ED - 4; d0 += 4) {
#pragma unroll
        for (int j = 0; j < 4; j++) nxt[j] = ecol[(d0 + 4 + j) * ET_LD];
        body(d0, cur);
#pragma unroll
        for (int j = 0; j < 4; j++) cur[j] = nxt[j];
    }
    body(ED - 4, cur);

    if (active) {
        int e = (c == NUM_ENT) ? 0 : c + 1;
#pragma unroll
        for (int bp = 0; bp < 4; bp++) {
            u64 a = acc[bp];
            float lo = __int_as_float((int)(a & 0xffffffffULL));
            float hi = __int_as_float((int)(a >> 32));
            int b = 8 * by + 2 * bp;
            out[(size_t)b * NE_OUT + e]       = -lo;
            out[(size_t)(b + 1) * NE_OUT + e] = -hi;
        }
    }
}

// ---------------- launcher ----------------
extern "C" void kernel_launch(void* const* d_in, const int* in_sizes, int n_in,
                              void* d_out, int out_size) {
    const float* ent   = (const float*)d_in[0];
    const float* other = (const float*)d_in[1];
    const float* W     = (const float*)d_in[2];
    const void*  ids   = d_in[3];
    const int*   mp    = (n_in > 4) ? (const int*)d_in[4] : nullptr;

    cudaFuncSetAttribute(gemm_bf16_kernel,
                         cudaFuncAttributeMaxDynamicSharedMemorySize, GEMM_SMEM);

    convB_kernel<<<(FD * ED + 255) / 256, 256>>>(W);
    fill_kernel<<<(103 * ED + 255) / 256, 256>>>(other);
    decode_ids_kernel<<<1, 32>>>(ids, mp);
    gemm_bf16_kernel<<<(NUM_ENT + BM - 1) / BM, 512, GEMM_SMEM>>>(ent);
    qsum_kernel<<<BATCH, 256>>>();
    dim3 sg((NE_OUT + 255) / 256, 4);          // 157 x 4
    score_kernel<<<sg, 256>>>((float*)d_out);
}

// round 11
// speedup vs baseline: 1.5407x; 1.0321x over previous
#include <cuda_runtime.h>
#include <cuda_bf16.h>
#include <cstdint>

#define NUM_ENT 40000
#define ED      256
#define FD      768
#define BATCH   32
#define NE_OUT  (NUM_ENT + 1)
#define ET_LD   40128

typedef unsigned long long u64;

// g_Et stores NEGATED values. Column map:
//   col c in [0,40000) : -ent_proj[c] (unity row c+1)
//   col 40000+r        : -other_emb[r] (unity rows 0, 40001..40102)
__device__ float          g_Et[ED * ET_LD];
__device__ __nv_bfloat16  g_Bb[FD * ED];
__device__ float          g_qsum[ED * BATCH];
__device__ int            g_qcol[BATCH * 2];

// ---------------- helpers ----------------
__device__ __forceinline__ u64 addf32x2(u64 a, u64 b) {
    u64 r;
    asm("add.rn.f32x2 %0, %1, %2;" : "=l"(r) : "l"(a), "l"(b));
    return r;
}
__device__ __forceinline__ u64 pack2(float x) {
    u64 r;
    asm("mov.b64 %0, {%1,%1};" : "=l"(r) : "f"(x));
    return r;
}
__device__ __forceinline__ void ldsm4(uint32_t r[4], uint32_t addr) {
    asm volatile("ldmatrix.sync.aligned.m8n8.x4.shared.b16 {%0,%1,%2,%3}, [%4];"
                 : "=r"(r[0]), "=r"(r[1]), "=r"(r[2]), "=r"(r[3])
                 : "r"(addr));
}
__device__ __forceinline__ void mma16816(float c[4], const uint32_t a[4],
                                         uint32_t b0, uint32_t b1) {
    asm volatile(
        "mma.sync.aligned.m16n8k16.row.col.f32.bf16.bf16.f32 "
        "{%0,%1,%2,%3}, {%4,%5,%6,%7}, {%8,%9}, {%0,%1,%2,%3};"
        : "+f"(c[0]), "+f"(c[1]), "+f"(c[2]), "+f"(c[3])
        : "r"(a[0]), "r"(a[1]), "r"(a[2]), "r"(a[3]), "r"(b0), "r"(b1));
}
__device__ __forceinline__ uint32_t smaddr(const void* p) {
    return (uint32_t)__cvta_generic_to_shared(p);
}

// ---------------- prep: convB + fill edges + decode ids (ONE kernel) ---------
__global__ void prep_kernel(const float* __restrict__ W,
                            const float* __restrict__ other,
                            const void* __restrict__ ids_raw,
                            const int* __restrict__ mp_ptr) {
    int i = blockIdx.x * 256 + threadIdx.x;
    if (i < FD * ED) g_Bb[i] = __float2bfloat16(W[i]);
    if (i < 103 * ED) {
        int r = i / ED, d = i % ED;
        g_Et[d * ET_LD + NUM_ENT + r] = -other[i];
    }
    if (blockIdx.x == 0 && threadIdx.x == 0) {
        const int* p = (const int*)ids_raw;
        bool is64 = true;
        for (int k = 1; k < BATCH * 3; k += 2)
            if (p[k] != 0) { is64 = false; break; }
        int mp = 2;
        if (mp_ptr) {
            int im = *mp_ptr;
            if (im >= 0 && im < 3) mp = im;
            else {
                float f = __int_as_float(im);
                if (f >= 0.f && f < 3.f) mp = (int)f;
            }
        }
        for (int b = 0; b < BATCH; b++)
            for (int j = 0; j < 2; j++) {
                int col3 = (j < mp) ? j : j + 1;
                int idx  = b * 3 + col3;
                int id   = is64 ? (int)((const long long*)ids_raw)[idx] : p[idx];
                int col  = (id == 0) ? NUM_ENT : (id <= NUM_ENT ? id - 1 : id);
                g_qcol[b * 2 + j] = col;
            }
    }
}

// ---------------- GEMM: Et[n][bm0+m] = -sum_k A[m,k]*W[n,k] ----------------
// BM=128, BN=256, BK=64, 512 threads (4m x 4n), warp tile 32x64, 3-stage smem.
#define BM       128
#define BK       64
#define ASTRIDE  72
#define A_ST     (BM * ASTRIDE)          // 9216 bf16
#define B_ST     (ED * ASTRIDE)          // 18432 bf16
#define STG_EL   (A_ST + B_ST)           // 27648 bf16 per stage
#define GEMM_SMEM (3 * STG_EL * 2)       // 165888 B

__global__ void __launch_bounds__(512, 1) gemm_bf16_kernel(const float* __restrict__ A) {
    extern __shared__ __nv_bfloat16 sm[];

    const int tid  = threadIdx.x;
    const int lane = tid & 31;
    const int warp = tid >> 5;
    const int wm   = warp >> 2;
    const int wn   = warp & 3;
    const int bm0  = blockIdx.x * BM;

    float acc[2][8][4];
#pragma unroll
    for (int i = 0; i < 2; i++)
#pragma unroll
        for (int j = 0; j < 8; j++)
#pragma unroll
            for (int k = 0; k < 4; k++) acc[i][j][k] = 0.f;

    float4 va[2];
    uint4  vb[2];

    auto sA = [&](int s) { return sm + s * STG_EL; };
    auto sB = [&](int s) { return sm + s * STG_EL + A_ST; };

    // A: 128 rows x 16 f4-slots; s = tid + 512*(2h+i): row=s>>4, slot=s&15
    auto loadHalfA = [&](int kc, int h) {
#pragma unroll
        for (int i = 0; i < 2; i++) {
            int s = tid + 512 * (2 * h + i);
            int r = s >> 4, sl = s & 15;
            if (bm0 + r < NUM_ENT)
                va[i] = *(const float4*)(A + (size_t)(bm0 + r) * FD + kc + sl * 4);
            else
                va[i] = make_float4(0.f, 0.f, 0.f, 0.f);
        }
    };
    auto stsHalfA = [&](int st, int h) {
#pragma unroll
        for (int i = 0; i < 2; i++) {
            int s = tid + 512 * (2 * h + i);
            int r = s >> 4, sl = s & 15;
            __nv_bfloat162 p0 = __floats2bfloat162_rn(va[i].x, va[i].y);
            __nv_bfloat162 p1 = __floats2bfloat162_rn(va[i].z, va[i].w);
            uint32_t u0 = *(uint32_t*)&p0, u1 = *(uint32_t*)&p1;
            uint32_t ad = smaddr(&sA(st)[r * ASTRIDE + sl * 4]);
            asm volatile("st.shared.v2.b32 [%0], {%1,%2};"
                         :: "r"(ad), "r"(u0), "r"(u1) : "memory");
        }
    };
    // B: 256 rows x 8 u4-slots
    auto loadHalfB = [&](int kc, int h) {
#pragma unroll
        for (int i = 0; i < 2; i++) {
            int s = tid + 512 * (2 * h + i);
            int r = s >> 3, q = s & 7;
            vb[i] = *(const uint4*)((const __nv_bfloat16*)g_Bb +
                                    (size_t)r * FD + kc + q * 8);
        }
    };
    auto stsHalfB = [&](int st, int h) {
#pragma unroll
        for (int i = 0; i < 2; i++) {
            int s = tid + 512 * (2 * h + i);
            int r = s >> 3, q = s & 7;
            *(uint4*)&sB(st)[r * ASTRIDE + q * 8] = vb[i];
        }
    };

    const int quad = lane >> 3, l8 = lane & 7;
    const int arow_l = (quad & 1) * 8 + l8;
    const int acol_q = (quad >> 1) * 8;
    const int brow_l = (quad >> 1) * 8 + l8;
    const int bcol_q = (quad & 1) * 8;

    auto mmaSub = [&](int st, int ks) {
        const int k0 = ks * 16;
        uint32_t a[2][4], b[4][4];
#pragma unroll
        for (int mf = 0; mf < 2; mf++) {
            uint32_t ad = smaddr(&sA(st)[(wm * 32 + mf * 16 + arow_l) * ASTRIDE +
                                         k0 + acol_q]);
            ldsm4(a[mf], ad);
        }
#pragma unroll
        for (int nf2 = 0; nf2 < 4; nf2++) {
            uint32_t ad = smaddr(&sB(st)[(wn * 64 + nf2 * 16 + brow_l) * ASTRIDE +
                                         k0 + bcol_q]);
            ldsm4(b[nf2], ad);
        }
#pragma unroll
        for (int mf = 0; mf < 2; mf++)
#pragma unroll
            for (int nt = 0; nt < 8; nt++)
                mma16816(acc[mf][nt], a[mf],
                         b[nt >> 1][(nt & 1) * 2],
                         b[nt >> 1][(nt & 1) * 2 + 1]);
    };

    const int NC = FD / BK;    // 12
    // prologue: chunks 0,1 -> stages 0,1
    loadHalfA(0, 0);  loadHalfB(0, 0);  stsHalfA(0, 0); stsHalfB(0, 0);
    loadHalfA(0, 1);  loadHalfB(0, 1);  stsHalfA(0, 1); stsHalfB(0, 1);
    loadHalfA(BK, 0); loadHalfB(BK, 0); stsHalfA(1, 0); stsHalfB(1, 0);
    loadHalfA(BK, 1); loadHalfB(BK, 1); stsHalfA(1, 1); stsHalfB(1, 1);

#pragma unroll 1
    for (int c = 0; c < NC; c++) {
        __syncthreads();                 // all warps done iter c-1 -> slot (c+2)%3 free
        const int st = c % 3;
        const int ns = (c + 2) % 3;
        const int kc2 = (c + 2) * BK;
        const bool more = (c + 2 < NC);
        if (more) { loadHalfA(kc2, 0); loadHalfB(kc2, 0); }
        mmaSub(st, 0);
        mmaSub(st, 1);
        if (more) {
            stsHalfA(ns, 0); stsHalfB(ns, 0);
            loadHalfA(kc2, 1); loadHalfB(kc2, 1);
        }
        mmaSub(st, 2);
        mmaSub(st, 3);
        if (more) { stsHalfA(ns, 1); stsHalfB(ns, 1); }
    }
    __syncthreads();

    // epilogue: 2 rounds, 2 buffers each (8 warps store per round), NEGATED
    float* s_out = (float*)sm;           // [2][64][132] = 67.6 KB
    const int g = lane >> 2, tg = lane & 3;
#pragma unroll
    for (int pair = 0; pair < 2; pair++) {
        if ((wn >> 1) == pair) {
            float* buf = s_out + (wn & 1) * (64 * 132);
#pragma unroll
            for (int mf = 0; mf < 2; mf++)
#pragma unroll
                for (int nt = 0; nt < 8; nt++) {
                    int srow = nt * 8 + tg * 2;
                    int scol = wm * 32 + mf * 16 + g;
                    buf[srow * 132 + scol]           = -acc[mf][nt][0];
                    buf[(srow + 1) * 132 + scol]     = -acc[mf][nt][1];
                    buf[srow * 132 + scol + 8]       = -acc[mf][nt][2];
                    buf[(srow + 1) * 132 + scol + 8] = -acc[mf][nt][3];
                }
        }
        __syncthreads();
#pragma unroll
        for (int i = 0; i < 8; i++) {
            int idx = tid + i * 512;     // 0..4095
            int buf = idx >> 11;         // 0..1
            int n   = (idx >> 5) & 63;
            int m4  = idx & 31;
            if (bm0 + m4 * 4 + 4 <= NUM_ENT) {
                float4 v = *(float4*)&s_out[buf * (64 * 132) + n * 132 + m4 * 4];
                int nrow = (pair * 2 + buf) * 64 + n;
                *(float4*)&g_Et[(size_t)nrow * ET_LD + bm0 + m4 * 4] = v;
            }
        }
        __syncthreads();
    }
}

// ---------------- query_sum ----------------
__global__ void __launch_bounds__(256) qsum_kernel() {
    __shared__ float s_red[2][8];
    const int b = blockIdx.x, tid = threadIdx.x;
    const int c0 = g_qcol[b * 2], c1 = g_qcol[b * 2 + 1];

    const int d = tid;
    float v0 = g_Et[d * ET_LD + c0];
    float v1 = g_Et[d * ET_LD + c1];
    float ss0 = v0 * v0, ss1 = v1 * v1;
#pragma unroll
    for (int o = 16; o > 0; o >>= 1) {
        ss0 += __shfl_xor_sync(0xffffffffu, ss0, o);
        ss1 += __shfl_xor_sync(0xffffffffu, ss1, o);
    }
    if ((tid & 31) == 0) { s_red[0][tid >> 5] = ss0; s_red[1][tid >> 5] = ss1; }
    __syncthreads();
    ss0 = 0.f; ss1 = 0.f;
#pragma unroll
    for (int w = 0; w < 8; w++) { ss0 += s_red[0][w]; ss1 += s_red[1][w]; }
    float r0 = -1.0f / fmaxf(sqrtf(ss0), 1e-12f);
    float r1 = -1.0f / fmaxf(sqrtf(ss1), 1e-12f);
    g_qsum[d * BATCH + b] = v0 * r0 + v1 * r1;
}

// ---------------- score: 1 col/thread, prefetch distance 8 ----------------
__global__ void __launch_bounds__(256) score_kernel(float* __restrict__ out) {
    __shared__ u64 sq[ED][4];
    const int tid = threadIdx.x;
    const int by  = blockIdx.y;

    {
        float4* dst = (float4*)&sq[0][0];
#pragma unroll
        for (int i = 0; i < 2; i++) {
            int idx = tid + i * 256;
            int d = idx >> 1, h = idx & 1;
            dst[d * 2 + h] = *(const float4*)(g_qsum + d * BATCH + by * 8 + h * 4);
        }
    }
    __syncthreads();

    const int c = blockIdx.x * 256 + tid;
    const bool active = (c <= NUM_ENT);
    const float* ecol = g_Et + (active ? c : 0);

    u64 acc[4];
#pragma unroll
    for (int i = 0; i < 4; i++) acc[i] = 0ULL;

    float cur[4], mid[4], nxt[4];
#pragma unroll
    for (int j = 0; j < 4; j++) cur[j] = ecol[j * ET_LD];
#pragma unroll
    for (int j = 0; j < 4; j++) mid[j] = ecol[(4 + j) * ET_LD];

    const u64 MSK = 0x7FFFFFFF7FFFFFFFULL;
    auto body = [&](int d0, const float cv[4]) {
        u64 q[4][4];
#pragma unroll
        for (int j = 0; j < 4; j++) {
            ulonglong2 t0 = *(const ulonglong2*)&sq[d0 + j][0];
            ulonglong2 t1 = *(const ulonglong2*)&sq[d0 + j][2];
            q[j][0] = t0.x; q[j][1] = t0.y; q[j][2] = t1.x; q[j][3] = t1.y;
        }
#pragma unroll
        for (int j = 0; j < 4; j++) {
            u64 e = pack2(cv[j]);
#pragma unroll
            for (int bp = 0; bp < 4; bp++)
                acc[bp] = addf32x2(acc[bp], addf32x2(q[j][bp], e) & MSK);
        }
    };

    // prefetch 8 d-rows ahead (3-buffer rotation)
    for (int d0 = 0; d0 < ED - 8; d0 += 4) {
#pragma unroll
        for (int j = 0; j < 4; j++) nxt[j] = ecol[(d0 + 8 + j) * ET_LD];
        body(d0, cur);
#pragma unroll
        for (int j = 0; j < 4; j++) { cur[j] = mid[j]; mid[j] = nxt[j]; }
    }
    body(ED - 8, cur);
    body(ED - 4, mid);

    if (active) {
        int e = (c == NUM_ENT) ? 0 : c + 1;
#pragma unroll
        for (int bp = 0; bp < 4; bp++) {
            u64 a = acc[bp];
            float lo = __int_as_float((int)(a & 0xffffffffULL));
            float hi = __int_as_float((int)(a >> 32));
            int b = 8 * by + 2 * bp;
            out[(size_t)b * NE_OUT + e]       = -lo;
            out[(size_t)(b + 1) * NE_OUT + e] = -hi;
        }
    }
}

// ---------------- launcher ----------------
extern "C" void kernel_launch(void* const* d_in, const int* in_sizes, int n_in,
                              void* d_out, int out_size) {
    const float* ent   = (const float*)d_in[0];
    const float* other = (const float*)d_in[1];
    const float* W     = (const float*)d_in[2];
    const void*  ids   = d_in[3];
    const int*   mp    = (n_in > 4) ? (const int*)d_in[4] : nullptr;

    cudaFuncSetAttribute(gemm_bf16_kernel,
                         cudaFuncAttributeMaxDynamicSharedMemorySize, GEMM_SMEM);

    prep_kernel<<<(FD * ED + 255) / 256, 256>>>(W, other, ids, mp);
    gemm_bf16_kernel<<<(NUM_ENT + BM - 1) / BM, 512, GEMM_SMEM>>>(ent);
    qsum_kernel<<<BATCH, 256>>>();
    dim3 sg((NE_OUT + 255) / 256, 4);          // 157 x 4
    score_kernel<<<sg, 256>>>((float*)d_out);
}